// round 2
// baseline (speedup 1.0000x reference)
#include <cuda_runtime.h>
#include <cuda_bf16.h>

// Problem constants (fixed by the reference)
#define T_MAX  8192
#define D_DIM  1024
#define E_NUM  8
#define IMOE   1024
#define ISH    4096

// ---------------------------------------------------------------------------
// Device scratch (allocation-free rule: __device__ globals)
// ---------------------------------------------------------------------------
__device__ __align__(256) float g_bufA [2u * T_MAX * IMOE]; // gathered gate-preact -> h (in place)
__device__ __align__(256) float g_y    [2u * T_MAX * IMOE]; // gathered down-proj outputs
__device__ __align__(256) float g_bufSh[(size_t)T_MAX * ISH]; // shared gate-preact -> h (in place)
__device__ __align__(256) float g_ysh  [(size_t)T_MAX * D_DIM]; // shared down-proj output

__device__ int   g_counts[E_NUM];
__device__ int   g_fill[E_NUM];
__device__ int   g_offs[E_NUM];
__device__ int   g_topE[2 * T_MAX];
__device__ float g_topW[2 * T_MAX];
__device__ float g_sgate[T_MAX];
__device__ int   g_gatherTok[2 * T_MAX];
__device__ int   g_slotRow[2 * T_MAX];

// ---------------------------------------------------------------------------
// Packed f32x2 helpers (FFMA2 — 2x fp32 FMA throughput vs 3-reg FFMA on B300)
// ---------------------------------------------------------------------------
__device__ __forceinline__ void fma2(unsigned long long& d, unsigned long long a,
                                     unsigned long long b) {
    asm("fma.rn.f32x2 %0, %1, %2, %0;" : "+l"(d) : "l"(a), "l"(b));
}
__device__ __forceinline__ unsigned long long rep2(float a) {
    unsigned long long r;
    asm("mov.b64 %0, {%1, %1};" : "=l"(r) : "f"(a));
    return r;
}
__device__ __forceinline__ float2 unpack2(unsigned long long v) {
    float2 f;
    asm("mov.b64 {%0, %1}, %2;" : "=f"(f.x), "=f"(f.y) : "l"(v));
    return f;
}

// ---------------------------------------------------------------------------
// 1) zero per-call metadata (graph replays must be stateless)
// ---------------------------------------------------------------------------
__global__ void zero_meta_kernel() {
    int i = threadIdx.x;
    if (i < E_NUM) { g_counts[i] = 0; g_fill[i] = 0; }
}

// ---------------------------------------------------------------------------
// 2) router: logits, softmax, top-2, renorm weights, shared gate, counts
//    one warp per token
// ---------------------------------------------------------------------------
__global__ void router_kernel(const float* __restrict__ x,
                              const float* __restrict__ gw,
                              const float* __restrict__ sgw,
                              float* __restrict__ logits_out,
                              int write_logits, int T) {
    int gwarp = (blockIdx.x * blockDim.x + threadIdx.x) >> 5;
    int lane  = threadIdx.x & 31;
    if (gwarp >= T) return;
    const float* xr = x + (size_t)gwarp * D_DIM;

    float acc[9];
#pragma unroll
    for (int i = 0; i < 9; ++i) acc[i] = 0.f;

    for (int d = lane; d < D_DIM; d += 32) {
        float xv = xr[d];
        const float4* g4 = (const float4*)(gw + (size_t)d * E_NUM);
        float4 w0 = g4[0], w1 = g4[1];
        acc[0] += xv * w0.x; acc[1] += xv * w0.y;
        acc[2] += xv * w0.z; acc[3] += xv * w0.w;
        acc[4] += xv * w1.x; acc[5] += xv * w1.y;
        acc[6] += xv * w1.z; acc[7] += xv * w1.w;
        acc[8] += xv * sgw[d];
    }
#pragma unroll
    for (int o = 16; o; o >>= 1)
#pragma unroll
        for (int i = 0; i < 9; ++i) acc[i] += __shfl_xor_sync(0xffffffffu, acc[i], o);

    if (lane == 0) {
        float mx = acc[0];
#pragma unroll
        for (int e = 1; e < E_NUM; ++e) mx = fmaxf(mx, acc[e]);
        float p[E_NUM], s = 0.f;
#pragma unroll
        for (int e = 0; e < E_NUM; ++e) { p[e] = expf(acc[e] - mx); s += p[e]; }
        float inv = 1.f / s;
#pragma unroll
        for (int e = 0; e < E_NUM; ++e) p[e] *= inv;

        int i0 = 0;
#pragma unroll
        for (int e = 1; e < E_NUM; ++e) if (p[e] > p[i0]) i0 = e;
        int i1 = (i0 == 0) ? 1 : 0;
#pragma unroll
        for (int e = 0; e < E_NUM; ++e) if (e != i0 && p[e] > p[i1]) i1 = e;

        float w0 = p[i0], w1 = p[i1];
        float invs = 1.f / fmaxf(w0 + w1, 1e-6f);
        g_topE[2 * gwarp]     = i0;
        g_topE[2 * gwarp + 1] = i1;
        g_topW[2 * gwarp]     = w0 * invs;
        g_topW[2 * gwarp + 1] = w1 * invs;
        g_sgate[gwarp] = 1.f / (1.f + expf(-acc[8]));
        atomicAdd(&g_counts[i0], 1);
        atomicAdd(&g_counts[i1], 1);
        if (write_logits) {
#pragma unroll
            for (int e = 0; e < E_NUM; ++e)
                logits_out[(size_t)gwarp * E_NUM + e] = acc[e];
        }
    }
}

// ---------------------------------------------------------------------------
// 3) exclusive scan of counts (tiny)
// ---------------------------------------------------------------------------
__global__ void scan_kernel() {
    if (threadIdx.x == 0) {
        int s = 0;
        for (int e = 0; e < E_NUM; ++e) { g_offs[e] = s; s += g_counts[e]; }
    }
}

// ---------------------------------------------------------------------------
// 4) gather: token -> expert-sorted row, and inverse slot map
// ---------------------------------------------------------------------------
__global__ void gather_kernel(int T) {
    int t = blockIdx.x * blockDim.x + threadIdx.x;
    if (t >= T) return;
#pragma unroll
    for (int k = 0; k < 2; ++k) {
        int e = g_topE[2 * t + k];
        int p = atomicAdd(&g_fill[e], 1);
        int row = g_offs[e] + p;
        g_gatherTok[row] = t;
        g_slotRow[2 * t + k] = row;
    }
}

// ---------------------------------------------------------------------------
// 5) SGEMM: 128x128x8 tile, 256 threads, 8x8/thread, double-buffered smem,
//    packed f32x2 FMAs. Supports: gathered A rows, per-expert (blockIdx.z)
//    weights/row-ranges, and fused silu(gate)*up epilogue (MODE==1).
// ---------------------------------------------------------------------------
template <int MODE> // 0: C = acc   1: C = silu(C_old) * acc
__global__ __launch_bounds__(256)
void sgemm_kernel(const float* __restrict__ A, const float* __restrict__ B,
                  float* __restrict__ C,
                  const int* __restrict__ gatherIdx, // may be null
                  const int* __restrict__ counts,    // null => M = Mfixed
                  const int* __restrict__ offs,
                  int Mfixed, int N, int K, long long bStride) {
    int e = blockIdx.z;
    int M, rowbase;
    if (counts) { M = counts[e]; rowbase = offs[e]; }
    else        { M = Mfixed;    rowbase = 0; }

    int bm = blockIdx.y * 128;
    if (bm >= M) return;
    int bn = blockIdx.x * 128;
    const float* Bp = B + (long long)e * bStride;

    __shared__ __align__(16) float As[2][8][128];
    __shared__ __align__(16) float Bs[2][8][128];

    int tid  = threadIdx.x;
    int arow = tid >> 1, acol = (tid & 1) * 4;
    int brow = tid >> 5, bcol = (tid & 31) * 4;

    int r = bm + arow;
    bool avalid = r < M;
    long long aoff = 0;
    if (avalid) {
        int grow = gatherIdx ? gatherIdx[rowbase + r] : (rowbase + r);
        aoff = (long long)grow * K + acol;
    }
    long long boff = (long long)brow * N + bn + bcol;

    float4 av = avalid ? *(const float4*)(A + aoff) : make_float4(0.f, 0.f, 0.f, 0.f);
    float4 bv = *(const float4*)(Bp + boff);
    As[0][acol + 0][arow] = av.x; As[0][acol + 1][arow] = av.y;
    As[0][acol + 2][arow] = av.z; As[0][acol + 3][arow] = av.w;
    *(float4*)&Bs[0][brow][bcol] = bv;
    __syncthreads();

    unsigned long long acc2[8][4];
#pragma unroll
    for (int i = 0; i < 8; ++i)
#pragma unroll
        for (int j = 0; j < 4; ++j) acc2[i][j] = 0ull;

    int tm = (tid >> 4) * 8;
    int tn = (tid & 15) * 8;
    int nt = K / 8;

    for (int kt = 0; kt < nt; ++kt) {
        int cur = kt & 1;
        float4 avn, bvn;
        bool more = (kt + 1) < nt;
        if (more) {
            avn = avalid ? *(const float4*)(A + aoff + (long long)(kt + 1) * 8)
                         : make_float4(0.f, 0.f, 0.f, 0.f);
            bvn = *(const float4*)(Bp + boff + (long long)(kt + 1) * 8 * N);
        }
#pragma unroll
        for (int k = 0; k < 8; ++k) {
            const float* asrc = &As[cur][k][tm];
            float4 a0 = *(const float4*)(asrc);
            float4 a1 = *(const float4*)(asrc + 4);
            const unsigned long long* bsrc =
                (const unsigned long long*)&Bs[cur][k][tn];
            unsigned long long b2[4] = {bsrc[0], bsrc[1], bsrc[2], bsrc[3]};
            float a[8] = {a0.x, a0.y, a0.z, a0.w, a1.x, a1.y, a1.z, a1.w};
#pragma unroll
            for (int i = 0; i < 8; ++i) {
                unsigned long long aa = rep2(a[i]);
#pragma unroll
                for (int j = 0; j < 4; ++j) fma2(acc2[i][j], aa, b2[j]);
            }
        }
        if (more) {
            int nxt = cur ^ 1;
            As[nxt][acol + 0][arow] = avn.x; As[nxt][acol + 1][arow] = avn.y;
            As[nxt][acol + 2][arow] = avn.z; As[nxt][acol + 3][arow] = avn.w;
            *(float4*)&Bs[nxt][brow][bcol] = bvn;
            __syncthreads();
        }
    }

    // epilogue
#pragma unroll
    for (int i = 0; i < 8; ++i) {
        int rr = bm + tm + i;
        if (rr >= M) break;
        float* crow = C + (long long)(rowbase + rr) * N + bn + tn;
#pragma unroll
        for (int j2 = 0; j2 < 4; ++j2) {
            float2 v = unpack2(acc2[i][j2]);
            if (MODE == 0) {
                *(float2*)(crow + 2 * j2) = v;
            } else {
                float2 g = *(const float2*)(crow + 2 * j2);
                float sx = g.x / (1.f + expf(-g.x));
                float sy = g.y / (1.f + expf(-g.y));
                float2 o;
                o.x = sx * v.x;
                o.y = sy * v.y;
                *(float2*)(crow + 2 * j2) = o;
            }
        }
    }
}

// ---------------------------------------------------------------------------
// 6) combine: out[t] = w0*y[r0] + w1*y[r1] + sgate*ysh[t]
// ---------------------------------------------------------------------------
__global__ void combine_kernel(float* __restrict__ out, int T) {
    int idx = blockIdx.x * blockDim.x + threadIdx.x;
    int total = T * (D_DIM / 4);
    if (idx >= total) return;
    int t = idx >> 8;  // D_DIM/4 = 256
    int c = idx & 255;
    int r0 = g_slotRow[2 * t], r1 = g_slotRow[2 * t + 1];
    float w0 = g_topW[2 * t], w1 = g_topW[2 * t + 1];
    float sgt = g_sgate[t];
    const float4* y4 = (const float4*)g_y;
    const float4* s4 = (const float4*)g_ysh;
    float4 a  = y4[(size_t)r0 * 256 + c];
    float4 b  = y4[(size_t)r1 * 256 + c];
    float4 sh = s4[(size_t)t * 256 + c];
    float4 o;
    o.x = w0 * a.x + w1 * b.x + sgt * sh.x;
    o.y = w0 * a.y + w1 * b.y + sgt * sh.y;
    o.z = w0 * a.z + w1 * b.z + sgt * sh.z;
    o.w = w0 * a.w + w1 * b.w + sgt * sh.w;
    ((float4*)out)[idx] = o;
}

// ---------------------------------------------------------------------------
// host launcher — graph-capturable, allocation-free
// ---------------------------------------------------------------------------
extern "C" void kernel_launch(void* const* d_in, const int* in_sizes, int n_in,
                              void* d_out, int out_size) {
    const float* x   = (const float*)d_in[0]; // [T, D]
    const float* gw  = (const float*)d_in[1]; // [D, E]
    const float* eg  = (const float*)d_in[2]; // [E, D, IMOE]
    const float* eu  = (const float*)d_in[3]; // [E, D, IMOE]
    const float* ed  = (const float*)d_in[4]; // [E, IMOE, D]
    const float* sg  = (const float*)d_in[5]; // [D, ISH]
    const float* su  = (const float*)d_in[6]; // [D, ISH]
    const float* sd  = (const float*)d_in[7]; // [ISH, D]
    const float* sgw = (const float*)d_in[8]; // [D, 1]
    float* out = (float*)d_out;

    int T = in_sizes[0] / D_DIM;

    float *bufA, *yb, *bufSh, *ysh;
    int *gtok, *cnts, *offs;
    cudaGetSymbolAddress((void**)&bufA,  g_bufA);
    cudaGetSymbolAddress((void**)&yb,    g_y);
    cudaGetSymbolAddress((void**)&bufSh, g_bufSh);
    cudaGetSymbolAddress((void**)&ysh,   g_ysh);
    cudaGetSymbolAddress((void**)&gtok,  g_gatherTok);
    cudaGetSymbolAddress((void**)&cnts,  g_counts);
    cudaGetSymbolAddress((void**)&offs,  g_offs);

    int write_logits = (out_size > T * D_DIM) ? 1 : 0;
    float* logits_out = out + (size_t)T * D_DIM;

    zero_meta_kernel<<<1, 32>>>();
    router_kernel<<<(T * 32 + 255) / 256, 256>>>(x, gw, sgw, logits_out,
                                                 write_logits, T);
    scan_kernel<<<1, 32>>>();
    gather_kernel<<<(T + 255) / 256, 256>>>(T);

    int mt = (T + 127) / 128;

    // MoE experts: gate -> bufA ; up (silu fuse) -> bufA ; down -> y
    dim3 gMoE(IMOE / 128, mt, E_NUM);
    sgemm_kernel<0><<<gMoE, 256>>>(x, eg, bufA, gtok, cnts, offs,
                                   0, IMOE, D_DIM, (long long)D_DIM * IMOE);
    sgemm_kernel<1><<<gMoE, 256>>>(x, eu, bufA, gtok, cnts, offs,
                                   0, IMOE, D_DIM, (long long)D_DIM * IMOE);
    dim3 gMoED(D_DIM / 128, mt, E_NUM);
    sgemm_kernel<0><<<gMoED, 256>>>(bufA, ed, yb, nullptr, cnts, offs,
                                    0, D_DIM, IMOE, (long long)IMOE * D_DIM);

    // Shared expert: gate -> bufSh ; up (silu fuse) -> bufSh ; down -> ysh
    dim3 gShGU(ISH / 128, mt, 1);
    sgemm_kernel<0><<<gShGU, 256>>>(x, sg, bufSh, nullptr, nullptr, nullptr,
                                    T, ISH, D_DIM, 0);
    sgemm_kernel<1><<<gShGU, 256>>>(x, su, bufSh, nullptr, nullptr, nullptr,
                                    T, ISH, D_DIM, 0);
    dim3 gShD(D_DIM / 128, mt, 1);
    sgemm_kernel<0><<<gShD, 256>>>(bufSh, sd, ysh, nullptr, nullptr, nullptr,
                                   T, D_DIM, ISH, 0);

    combine_kernel<<<(T * (D_DIM / 4) + 255) / 256, 256>>>(out, T);
}